// round 13
// baseline (speedup 1.0000x reference)
#include <cuda_runtime.h>
#include <cuda_fp16.h>
#include <math_constants.h>
#include <cstdint>

#define BB 8
#define TT 2048
#define CC 1024
#define SS 256
#define KTOP 8

// ---------------------------------------------------------------------------
// helpers
// ---------------------------------------------------------------------------
__device__ __forceinline__ uint32_t smem_u32(const void* p) {
    uint32_t a;
    asm("{ .reg .u64 t; cvta.to.shared.u64 t, %1; cvt.u32.u64 %0, t; }" : "=r"(a) : "l"(p));
    return a;
}
__device__ __forceinline__ uint32_t pack_h2(float a, float b) {
    __half2 h = __floats2half2_rn(a, b);
    return *reinterpret_cast<uint32_t*>(&h);
}
__device__ __forceinline__ float2 unpack_h2(uint32_t u) {
    __half2 h = *reinterpret_cast<__half2*>(&u);
    return __half22float2(h);
}
__device__ __forceinline__ void mma_f16(float* d, const uint32_t* a, const uint32_t* b) {
    asm volatile(
        "mma.sync.aligned.m16n8k16.row.col.f32.f16.f16.f32 "
        "{%0,%1,%2,%3}, {%4,%5,%6,%7}, {%8,%9}, {%0,%1,%2,%3};"
        : "+f"(d[0]), "+f"(d[1]), "+f"(d[2]), "+f"(d[3])
        : "r"(a[0]), "r"(a[1]), "r"(a[2]), "r"(a[3]), "r"(b[0]), "r"(b[1]));
}
__device__ __forceinline__ void ldsm_x4(uint32_t* r, uint32_t addr) {
    asm volatile("ldmatrix.sync.aligned.m8n8.x4.shared.b16 {%0,%1,%2,%3}, [%4];"
        : "=r"(r[0]), "=r"(r[1]), "=r"(r[2]), "=r"(r[3]) : "r"(addr));
}
__device__ __forceinline__ void ldsm_x2(uint32_t* r, uint32_t addr) {
    asm volatile("ldmatrix.sync.aligned.m8n8.x2.shared.b16 {%0,%1}, [%2];"
        : "=r"(r[0]), "=r"(r[1]) : "r"(addr));
}
__device__ __forceinline__ void cp16(uint32_t saddr, const void* gaddr) {
    asm volatile("cp.async.cg.shared.global [%0], [%1], 16;" :: "r"(saddr), "l"(gaddr));
}
// swizzled byte offset within a tile region: row (64B pitch), 16B unit u (0..3)
__device__ __forceinline__ uint32_t swz(int row, int u) {
    return (uint32_t)(row * 64 + ((u ^ ((row >> 1) & 3)) << 4));
}

#define WSCALE 32.0f            // weight pre-scale (power of 2; exact)

// ---------------------------------------------------------------------------
// scratch
// ---------------------------------------------------------------------------
__device__ __half g_xh[BB * TT * CC];
__device__ __half g_xl[BB * TT * CC];
__device__ __half g_sh[BB * SS * CC];
__device__ __half g_sl[BB * SS * CC];
__device__ __half g_kqh[BB * SS * CC];      // kq' (scaled by 1024)
__device__ __half g_kql[BB * SS * CC];
__device__ float  g_pv[BB * SS * CC];       // pv (true scale)
__device__ float  g_scores[BB * TT * SS];
// A-buffer for weight products: slot0 = 32*Wq^T, slot1 = 32*Wp
__device__ __half g_wah[2 * CC * CC];
__device__ __half g_wal[2 * CC * CC];
// B-buffer: slot0 = 32*Wk^T, slot1 = 32*Wv^T
__device__ __half g_wbh[2 * CC * CC];
__device__ __half g_wbl[2 * CC * CC];
// products: slot0 = G' = 1024*Wq^T·Wk, slot1 = H' = 1024*Wp·Wv
__device__ __half g_wgh[2 * CC * CC];
__device__ __half g_wgl[2 * CC * CC];

// ---------------------------------------------------------------------------
// fused: x -> xh/xl AND slots (mean of 8 rows) -> sh/sl. One read of x.
// ---------------------------------------------------------------------------
__global__ void pool_cvt_kernel(const float* __restrict__ x) {
    int i = blockIdx.x * 256 + threadIdx.x;     // [0, BB*SS*CC)
    int c = i & (CC - 1);
    int bs = i >> 10;
    int s = bs & (SS - 1);
    int b = bs >> 8;
    const size_t base = ((size_t)b * TT + (size_t)s * 8) * CC + c;
    float sum = 0.f;
#pragma unroll
    for (int u = 0; u < 8; u++) {
        float v = x[base + (size_t)u * CC];
        sum += v;
        __half h = __float2half_rn(v);
        g_xh[base + (size_t)u * CC] = h;
        g_xl[base + (size_t)u * CC] = __float2half_rn(v - __half2float(h));
    }
    sum *= 0.125f;
    __half h = __float2half_rn(sum);
    g_sh[i] = h;
    g_sl[i] = __float2half_rn(sum - __half2float(h));
}

// ---------------------------------------------------------------------------
// batched weight prep (z selects which weight)
// z=0: Wq^T -> wah/wal slot0;  z=1: Wk^T -> wbh/wbl slot0;
// z=2: Wv^T -> wbh/wbl slot1;  z=3: Wp (no transpose) -> wah/wal slot1
// all scaled by WSCALE, split into fp16 hi/lo
// ---------------------------------------------------------------------------
__global__ void weight_prep(const float* __restrict__ w0, const float* __restrict__ w1,
                            const float* __restrict__ w2, const float* __restrict__ w3) {
    __shared__ float t[32][33];
    const int z = blockIdx.z;
    const int bx = blockIdx.x * 32, by = blockIdx.y * 32;
    const int tx = threadIdx.x, ty = threadIdx.y;   // (32, 8)

    if (z == 3) {   // straight copy-split of Wp into A slot1
        __half* oh = g_wah + (size_t)CC * CC;
        __half* ol = g_wal + (size_t)CC * CC;
#pragma unroll
        for (int j = 0; j < 4; j++) {
            size_t o = (size_t)(by + ty * 4 + j) * CC + bx + tx;
            float v = w3[o] * WSCALE;
            __half h = __float2half_rn(v);
            oh[o] = h;
            ol[o] = __float2half_rn(v - __half2float(h));
        }
        return;
    }

    const float* in = (z == 0) ? w0 : (z == 1) ? w1 : w2;
    __half* oh = (z == 0) ? g_wah : (z == 1) ? g_wbh : (g_wbh + (size_t)CC * CC);
    __half* ol = (z == 0) ? g_wal : (z == 1) ? g_wbl : (g_wbl + (size_t)CC * CC);

#pragma unroll
    for (int j = 0; j < 4; j++)
        t[ty * 4 + j][tx] = in[(size_t)(by + ty * 4 + j) * CC + bx + tx];
    __syncthreads();
#pragma unroll
    for (int j = 0; j < 4; j++) {
        float v = t[tx][ty * 4 + j] * WSCALE;
        __half h = __float2half_rn(v);
        size_t o = (size_t)(bx + ty * 4 + j) * CC + by + tx;
        oh[o] = h;
        ol[o] = __float2half_rn(v - __half2float(h));
    }
}

// ---------------------------------------------------------------------------
// Pipelined split-fp16 HMMA GEMM, CTA 128x128, BK=32, 8 warps (2m x 4n),
// warp tile 64x32. 2-stage cp.async (64KB total -> 2 CTAs/SM).
// nprod (per z: np0 for bz==0 else np1):
//   3: AhBh + AhBl + AlBh      2: AhBh + AlBh      1: AhBh
// unused lo tiles are not even loaded.
// mode 0: fp32 out (alpha). mode 1: fp16 hi/lo out (alpha).
// mode 2: z=0 hi/lo out (alpha), z=1 fp32 out (alpha2); cbase 0.
// ---------------------------------------------------------------------------
#define STAGES 2
#define STAGE_BYTES 32768
#define GEMM_SMEM (STAGES * STAGE_BYTES)

__global__ __launch_bounds__(256, 2)
void gemm_mma(const __half* __restrict__ Ah, const __half* __restrict__ Al,
              const __half* __restrict__ Bh, const __half* __restrict__ Bl,
              float* __restrict__ Cf, __half* __restrict__ Chi, __half* __restrict__ Clo,
              int M, int N, int K,
              long long sA, long long sB, long long sC,
              float alpha, float alpha2, int mode, int np0, int np1) {
    extern __shared__ __align__(16) char smem[];
    const uint32_t sb = smem_u32(smem);

    const int tid = threadIdx.x;
    const int wid = tid >> 5;
    const int lane = tid & 31;
    const int bz = blockIdx.z;
    const size_t m0 = (size_t)blockIdx.y * 128;
    const size_t n0 = (size_t)blockIdx.x * 128;

    const int nprod = (bz == 0) ? np0 : np1;
    const bool useAl = (nprod >= 2);
    const bool useBl = (nprod >= 3);

    const __half* gAh = Ah + (size_t)bz * (size_t)sA;
    const __half* gAl = Al + (size_t)bz * (size_t)sA;
    const __half* gBh = Bh + (size_t)bz * (size_t)sB;
    const __half* gBl = Bl + (size_t)bz * (size_t)sB;

    const int lrow = tid >> 1;
    const int lu   = (tid & 1) * 2;
    const size_t aoffg = (m0 + lrow) * (size_t)K;
    const size_t boffg = (n0 + lrow) * (size_t)K;

    const int nch = K >> 5;

#define LOAD_STAGE(stg) do { \
    const uint32_t st = sb + ((stg) % STAGES) * STAGE_BYTES; \
    const int kof = (stg) * 32; \
    _Pragma("unroll") \
    for (int j = 0; j < 2; j++) { \
        int u = lu + j; \
        uint32_t so = swz(lrow, u); \
        size_t goa = aoffg + kof + u * 8; \
        size_t gob = boffg + kof + u * 8; \
        cp16(st + so,         gAh + goa); \
        if (useAl) cp16(st + 8192 + so,  gAl + goa); \
        cp16(st + 16384 + so, gBh + gob); \
        if (useBl) cp16(st + 24576 + so, gBl + gob); \
    } \
} while (0)

    const int wm = wid >> 2;
    const int wn = wid & 3;

    float acc[4][4][4];
#pragma unroll
    for (int i = 0; i < 4; i++)
#pragma unroll
        for (int j = 0; j < 4; j++)
#pragma unroll
            for (int r = 0; r < 4; r++) acc[i][j][r] = 0.f;

    // prologue: one stage in flight
    LOAD_STAGE(0);
    asm volatile("cp.async.commit_group;" ::: "memory");

    for (int c = 0; c < nch; c++) {
        asm volatile("cp.async.wait_group 0;" ::: "memory");
        __syncthreads();

        if (c + 1 < nch) LOAD_STAGE(c + 1);
        asm volatile("cp.async.commit_group;" ::: "memory");

        const uint32_t st = sb + (c % STAGES) * STAGE_BYTES;
#pragma unroll
        for (int ks = 0; ks < 2; ks++) {
            uint32_t bhf[4][2], blf[4][2];
            const int rB0 = wn * 32 + (lane & 7);
            const int cuB = 2 * ks + ((lane >> 3) & 1);
#pragma unroll
            for (int fn = 0; fn < 4; fn++) {
                uint32_t ad = st + 16384 + swz(rB0 + 8 * fn, cuB);
                ldsm_x2(bhf[fn], ad);
                if (useBl) ldsm_x2(blf[fn], ad + 8192);
            }
#pragma unroll
            for (int fm = 0; fm < 4; fm++) {
                int rowA = wm * 64 + fm * 16 + (lane & 7) + ((lane >> 3) & 1) * 8;
                int cuA = 2 * ks + (lane >> 4);
                uint32_t ad = st + swz(rowA, cuA);
                uint32_t ah[4], al[4];
                ldsm_x4(ah, ad);
                if (useAl) ldsm_x4(al, ad + 8192);
#pragma unroll
                for (int fn = 0; fn < 4; fn++) mma_f16(acc[fm][fn], ah, bhf[fn]);
                if (useBl) {
#pragma unroll
                    for (int fn = 0; fn < 4; fn++) mma_f16(acc[fm][fn], ah, blf[fn]);
                }
                if (useAl) {
#pragma unroll
                    for (int fn = 0; fn < 4; fn++) mma_f16(acc[fm][fn], al, bhf[fn]);
                }
            }
        }
    }
#undef LOAD_STAGE

    // ---- epilogue ----
    int emode = mode;
    float a = alpha;
    if (mode == 2) { emode = (bz == 0) ? 1 : 0; if (bz == 1) a = alpha2; }
    const size_t cbase = (mode == 2) ? 0 : (size_t)bz * (size_t)sC;
    const int eg = lane >> 2;
    const int et = lane & 3;

#pragma unroll
    for (int fm = 0; fm < 4; fm++) {
        size_t row0 = m0 + wm * 64 + fm * 16 + eg;
#pragma unroll
        for (int fn = 0; fn < 4; fn++) {
            size_t col = n0 + wn * 32 + fn * 8 + et * 2;
            float c0 = a * acc[fm][fn][0];
            float c1 = a * acc[fm][fn][1];
            float c2 = a * acc[fm][fn][2];
            float c3 = a * acc[fm][fn][3];
            if (emode == 0) {
                *(float2*)(Cf + cbase + row0 * N + col)       = make_float2(c0, c1);
                *(float2*)(Cf + cbase + (row0 + 8) * N + col) = make_float2(c2, c3);
            } else {
                uint32_t h0 = pack_h2(c0, c1);
                float2 e0 = unpack_h2(h0);
                uint32_t l0 = pack_h2(c0 - e0.x, c1 - e0.y);
                uint32_t h1 = pack_h2(c2, c3);
                float2 e1 = unpack_h2(h1);
                uint32_t l1 = pack_h2(c2 - e1.x, c3 - e1.y);
                *(uint32_t*)(Chi + cbase + row0 * N + col)       = h0;
                *(uint32_t*)(Clo + cbase + row0 * N + col)       = l0;
                *(uint32_t*)(Chi + cbase + (row0 + 8) * N + col) = h1;
                *(uint32_t*)(Clo + cbase + (row0 + 8) * N + col) = l1;
            }
        }
    }
}

// ---------------------------------------------------------------------------
// top-8 + softmax + weighted PV gather; writes final output (x0.5 folded in)
// ---------------------------------------------------------------------------
__global__ void topk_gather_kernel(float* __restrict__ out) {
    const int warp_global = (blockIdx.x * blockDim.x + threadIdx.x) >> 5;
    const int lane = threadIdx.x & 31;
    const int b = warp_global >> 11;
    const int t = warp_global & (TT - 1);

    const float* srow = g_scores + ((long)b * TT + t) * SS;

    float vals[8];
#pragma unroll
    for (int i = 0; i < 8; i++) vals[i] = srow[lane + 32 * i];

    float w[KTOP];
    int   idx[KTOP];

#pragma unroll
    for (int r = 0; r < KTOP; r++) {
        float best = -CUDART_INF_F;
        int   bi = 0x7fffffff;
#pragma unroll
        for (int i = 0; i < 8; i++)
            if (vals[i] > best) { best = vals[i]; bi = lane + 32 * i; }
#pragma unroll
        for (int off = 16; off; off >>= 1) {
            float ov = __shfl_xor_sync(0xffffffffu, best, off);
            int   oi = __shfl_xor_sync(0xffffffffu, bi, off);
            if (ov > best || (ov == best && oi < bi)) { best = ov; bi = oi; }
        }
        w[r] = best;
        idx[r] = bi;
#pragma unroll
        for (int i = 0; i < 8; i++)
            if ((lane + 32 * i) == bi) vals[i] = -CUDART_INF_F;
    }

    float mx = w[0];
    float sum = 0.f;
#pragma unroll
    for (int r = 0; r < KTOP; r++) { w[r] = __expf(w[r] - mx); sum += w[r]; }
    float inv = 0.5f / sum;                         // RETRIEVAL_WEIGHT folded in
#pragma unroll
    for (int r = 0; r < KTOP; r++) w[r] *= inv;

    const float* pvb = g_pv + (long)b * SS * CC;
    float* o = out + ((long)b * TT + t) * CC;
#pragma unroll
    for (int it = 0; it < CC / 128; it++) {
        int c = lane * 4 + it * 128;
        float4 acc = make_float4(0.f, 0.f, 0.f, 0.f);
#pragma unroll
        for (int r = 0; r < KTOP; r++) {
            float4 vv = *(const float4*)(pvb + (long)idx[r] * CC + c);
            acc.x = fmaf(w[r], vv.x, acc.x);
            acc.y = fmaf(w[r], vv.y, acc.y);
            acc.z = fmaf(w[r], vv.z, acc.z);
            acc.w = fmaf(w[r], vv.w, acc.w);
        }
        *(float4*)(o + c) = acc;
    }
}

// ---------------------------------------------------------------------------
// launch
// ---------------------------------------------------------------------------
extern "C" void kernel_launch(void* const* d_in, const int* in_sizes, int n_in,
                              void* d_out, int out_size) {
    const float* x  = (const float*)d_in[0];
    const float* Wq = (const float*)d_in[1];
    const float* Wk = (const float*)d_in[2];
    const float* Wv = (const float*)d_in[3];
    const float* Wp = (const float*)d_in[4];
    float* out = (float*)d_out;

    void *pxh, *pxl, *psh, *psl, *pkqh, *pkql, *ppv, *psc;
    void *pwah, *pwal, *pwbh, *pwbl, *pwgh, *pwgl;
    cudaGetSymbolAddress(&pxh, g_xh);  cudaGetSymbolAddress(&pxl, g_xl);
    cudaGetSymbolAddress(&psh, g_sh);  cudaGetSymbolAddress(&psl, g_sl);
    cudaGetSymbolAddress(&pkqh, g_kqh); cudaGetSymbolAddress(&pkql, g_kql);
    cudaGetSymbolAddress(&ppv, g_pv);  cudaGetSymbolAddress(&psc, g_scores);
    cudaGetSymbolAddress(&pwah, g_wah); cudaGetSymbolAddress(&pwal, g_wal);
    cudaGetSymbolAddress(&pwbh, g_wbh); cudaGetSymbolAddress(&pwbl, g_wbl);
    cudaGetSymbolAddress(&pwgh, g_wgh); cudaGetSymbolAddress(&pwgl, g_wgl);

    __half* xh = (__half*)pxh;  __half* xl = (__half*)pxl;
    __half* sh = (__half*)psh;  __half* sl = (__half*)psl;
    __half* kqh = (__half*)pkqh; __half* kql = (__half*)pkql;
    float* pv = (float*)ppv; float* scores = (float*)psc;
    __half* wah = (__half*)pwah; __half* wal = (__half*)pwal;
    __half* wbh = (__half*)pwbh; __half* wbl = (__half*)pwbl;
    __half* wgh = (__half*)pwgh; __half* wgl = (__half*)pwgl;

    cudaFuncSetAttribute(gemm_mma, cudaFuncAttributeMaxDynamicSharedMemorySize, GEMM_SMEM);

    const long long CC2 = (long long)CC * CC;

    // 1) fused pool + x conversion; batched weight prep (Wq^T, Wk^T, Wv^T, Wp)
    pool_cvt_kernel<<<(BB * SS * CC) / 256, 256>>>(x);
    {
        dim3 tg(CC / 32, CC / 32, 4), tb(32, 8);
        weight_prep<<<tg, tb>>>(Wq, Wk, Wv, Wp);
    }

    // 2) weight products (batched z=2), hi/lo out, alpha=1 (keep x1024 scale):
    //    z=0: G' = (32Wq)^T·(32Wk), 3-product (feeds scores chain)
    //    z=1: H' = (32Wp)·(32Wv),   2-product (out path, loose budget)
    {
        dim3 grid(CC / 128, CC / 128, 2);
        gemm_mma<<<grid, 256, GEMM_SMEM>>>(wah, wal, wbh, wbl,
                                           nullptr, wgh, wgl, CC, CC, CC,
                                           CC2, CC2, CC2, 1.0f, 0.f, 1, 3, 2);
    }

    // 3) kq' + pv (batched z=2, mode 2):
    //    z=0: kq' = TN(slots, G') -> hi/lo, full 3-product (scores chain)
    //    z=1: pv  = TN(slots, H')·(1/1024) -> fp32, 1-product
    {
        dim3 grid(CC / 128, (BB * SS) / 128, 2);
        gemm_mma<<<grid, 256, GEMM_SMEM>>>(sh, sl, wgh, wgl,
                                           pv, kqh, kql, BB * SS, CC, CC,
                                           0, CC2, 0, 1.0f, 1.0f / 1024.0f, 2, 3, 1);
    }

    // 4) scores[b] = x[b] @ kq'[b]^T / (32*1024)  (batched over B, full 3-product)
    {
        dim3 grid(SS / 128, TT / 128, BB);
        gemm_mma<<<grid, 256, GEMM_SMEM>>>(xh, xl, kqh, kql, scores, nullptr, nullptr,
                                           TT, SS, CC,
                                           (long long)TT * CC, (long long)SS * CC, (long long)TT * SS,
                                           1.0f / 32768.0f, 0.f, 0, 3, 3);
    }

    // 5) top-8 + softmax + gather of pv -> out (0.5 folded in)
    topk_gather_kernel<<<(BB * TT) / 8, 256>>>(out);
}

// round 15
// speedup vs baseline: 1.0784x; 1.0784x over previous
#include <cuda_runtime.h>
#include <cuda_fp16.h>
#include <math_constants.h>
#include <cstdint>

#define BB 8
#define TT 2048
#define CC 1024
#define SS 256
#define KTOP 8

// ---------------------------------------------------------------------------
// helpers
// ---------------------------------------------------------------------------
__device__ __forceinline__ uint32_t smem_u32(const void* p) {
    uint32_t a;
    asm("{ .reg .u64 t; cvta.to.shared.u64 t, %1; cvt.u32.u64 %0, t; }" : "=r"(a) : "l"(p));
    return a;
}
__device__ __forceinline__ uint32_t pack_h2(float a, float b) {
    __half2 h = __floats2half2_rn(a, b);
    return *reinterpret_cast<uint32_t*>(&h);
}
__device__ __forceinline__ float2 unpack_h2(uint32_t u) {
    __half2 h = *reinterpret_cast<__half2*>(&u);
    return __half22float2(h);
}
__device__ __forceinline__ void mma_f16(float* d, const uint32_t* a, const uint32_t* b) {
    asm volatile(
        "mma.sync.aligned.m16n8k16.row.col.f32.f16.f16.f32 "
        "{%0,%1,%2,%3}, {%4,%5,%6,%7}, {%8,%9}, {%0,%1,%2,%3};"
        : "+f"(d[0]), "+f"(d[1]), "+f"(d[2]), "+f"(d[3])
        : "r"(a[0]), "r"(a[1]), "r"(a[2]), "r"(a[3]), "r"(b[0]), "r"(b[1]));
}
__device__ __forceinline__ void ldsm_x4(uint32_t* r, uint32_t addr) {
    asm volatile("ldmatrix.sync.aligned.m8n8.x4.shared.b16 {%0,%1,%2,%3}, [%4];"
        : "=r"(r[0]), "=r"(r[1]), "=r"(r[2]), "=r"(r[3]) : "r"(addr));
}
__device__ __forceinline__ void ldsm_x2(uint32_t* r, uint32_t addr) {
    asm volatile("ldmatrix.sync.aligned.m8n8.x2.shared.b16 {%0,%1}, [%2];"
        : "=r"(r[0]), "=r"(r[1]) : "r"(addr));
}
__device__ __forceinline__ void cp16(uint32_t saddr, const void* gaddr) {
    asm volatile("cp.async.cg.shared.global [%0], [%1], 16;" :: "r"(saddr), "l"(gaddr));
}
// swizzled byte offset within a tile region: row (64B pitch), 16B unit u (0..3)
__device__ __forceinline__ uint32_t swz(int row, int u) {
    return (uint32_t)(row * 64 + ((u ^ ((row >> 1) & 3)) << 4));
}

#define WSCALE 32.0f            // weight pre-scale (power of 2; exact)

// ---------------------------------------------------------------------------
// scratch
// ---------------------------------------------------------------------------
__device__ __half g_xh[BB * TT * CC];
__device__ __half g_xl[BB * TT * CC];
__device__ __half g_sh[BB * SS * CC];
__device__ __half g_sl[BB * SS * CC];
__device__ __half g_kqh[BB * SS * CC];      // kq' (scaled by 1024)
__device__ __half g_kql[BB * SS * CC];
__device__ float  g_pv[BB * SS * CC];       // pv (true scale)
__device__ float  g_scores[BB * TT * SS];
// A-buffer for weight products: slot0 = 32*Wq^T, slot1 = 32*Wp
__device__ __half g_wah[2 * CC * CC];
__device__ __half g_wal[2 * CC * CC];
// B-buffer: slot0 = 32*Wk^T, slot1 = 32*Wv^T
__device__ __half g_wbh[2 * CC * CC];
__device__ __half g_wbl[2 * CC * CC];
// products: slot0 = G' = 1024*Wq^T·Wk, slot1 = H' = 1024*Wp·Wv
__device__ __half g_wgh[2 * CC * CC];
__device__ __half g_wgl[2 * CC * CC];

// ---------------------------------------------------------------------------
// fused: x -> xh/xl AND slots (mean of 8 rows) -> sh/sl. One read of x.
// ---------------------------------------------------------------------------
__global__ void pool_cvt_kernel(const float* __restrict__ x) {
    int i = blockIdx.x * 256 + threadIdx.x;     // [0, BB*SS*CC)
    int c = i & (CC - 1);
    int bs = i >> 10;
    int s = bs & (SS - 1);
    int b = bs >> 8;
    const size_t base = ((size_t)b * TT + (size_t)s * 8) * CC + c;
    float sum = 0.f;
#pragma unroll
    for (int u = 0; u < 8; u++) {
        float v = x[base + (size_t)u * CC];
        sum += v;
        __half h = __float2half_rn(v);
        g_xh[base + (size_t)u * CC] = h;
        g_xl[base + (size_t)u * CC] = __float2half_rn(v - __half2float(h));
    }
    sum *= 0.125f;
    __half h = __float2half_rn(sum);
    g_sh[i] = h;
    g_sl[i] = __float2half_rn(sum - __half2float(h));
}

// ---------------------------------------------------------------------------
// batched weight prep (z selects which weight)
// z=0: Wq^T -> wah/wal slot0;  z=1: Wk^T -> wbh/wbl slot0;
// z=2: Wv^T -> wbh/wbl slot1;  z=3: Wp (no transpose) -> wah/wal slot1
// ---------------------------------------------------------------------------
__global__ void weight_prep(const float* __restrict__ w0, const float* __restrict__ w1,
                            const float* __restrict__ w2, const float* __restrict__ w3) {
    __shared__ float t[32][33];
    const int z = blockIdx.z;
    const int bx = blockIdx.x * 32, by = blockIdx.y * 32;
    const int tx = threadIdx.x, ty = threadIdx.y;   // (32, 8)

    if (z == 3) {   // straight copy-split of Wp into A slot1
        __half* oh = g_wah + (size_t)CC * CC;
        __half* ol = g_wal + (size_t)CC * CC;
#pragma unroll
        for (int j = 0; j < 4; j++) {
            size_t o = (size_t)(by + ty * 4 + j) * CC + bx + tx;
            float v = w3[o] * WSCALE;
            __half h = __float2half_rn(v);
            oh[o] = h;
            ol[o] = __float2half_rn(v - __half2float(h));
        }
        return;
    }

    const float* in = (z == 0) ? w0 : (z == 1) ? w1 : w2;
    __half* oh = (z == 0) ? g_wah : (z == 1) ? g_wbh : (g_wbh + (size_t)CC * CC);
    __half* ol = (z == 0) ? g_wal : (z == 1) ? g_wbl : (g_wbl + (size_t)CC * CC);

#pragma unroll
    for (int j = 0; j < 4; j++)
        t[ty * 4 + j][tx] = in[(size_t)(by + ty * 4 + j) * CC + bx + tx];
    __syncthreads();
#pragma unroll
    for (int j = 0; j < 4; j++) {
        float v = t[tx][ty * 4 + j] * WSCALE;
        __half h = __float2half_rn(v);
        size_t o = (size_t)(bx + ty * 4 + j) * CC + by + tx;
        oh[o] = h;
        ol[o] = __float2half_rn(v - __half2float(h));
    }
}

// ---------------------------------------------------------------------------
// Pipelined split-fp16 HMMA GEMM core, fully specialized on NPROD:
//   3: AhBh + AhBl + AlBh      2: AhBh + AlBh      1: AhBh
// CTA 128x128, BK=32, 8 warps (2m x 4n), warp tile 64x32; 2-stage cp.async.
// ---------------------------------------------------------------------------
#define STAGES 2
#define STAGE_BYTES 32768
#define GEMM_SMEM (STAGES * STAGE_BYTES)

template<int NPROD>
__device__ __forceinline__ void gemm_core(
    const __half* __restrict__ gAh, const __half* __restrict__ gAl,
    const __half* __restrict__ gBh, const __half* __restrict__ gBl,
    float* __restrict__ Cf, __half* __restrict__ Chi, __half* __restrict__ Clo,
    int N, int K, size_t m0, size_t n0, size_t cbase,
    float a, int emode, uint32_t sb) {

    constexpr bool useAl = (NPROD >= 2);
    constexpr bool useBl = (NPROD >= 3);

    const int tid = threadIdx.x;
    const int wid = tid >> 5;
    const int lane = tid & 31;

    const int lrow = tid >> 1;
    const int lu   = (tid & 1) * 2;
    const size_t aoffg = (m0 + lrow) * (size_t)K;
    const size_t boffg = (n0 + lrow) * (size_t)K;

    const int nch = K >> 5;

#define LOAD_STAGE(stg) do { \
    const uint32_t st = sb + ((stg) % STAGES) * STAGE_BYTES; \
    const int kof = (stg) * 32; \
    _Pragma("unroll") \
    for (int j = 0; j < 2; j++) { \
        int u = lu + j; \
        uint32_t so = swz(lrow, u); \
        size_t goa = aoffg + kof + u * 8; \
        size_t gob = boffg + kof + u * 8; \
        cp16(st + so,         gAh + goa); \
        if (useAl) cp16(st + 8192 + so,  gAl + goa); \
        cp16(st + 16384 + so, gBh + gob); \
        if (useBl) cp16(st + 24576 + so, gBl + gob); \
    } \
} while (0)

    const int wm = wid >> 2;
    const int wn = wid & 3;

    float acc[4][4][4];
#pragma unroll
    for (int i = 0; i < 4; i++)
#pragma unroll
        for (int j = 0; j < 4; j++)
#pragma unroll
            for (int r = 0; r < 4; r++) acc[i][j][r] = 0.f;

    LOAD_STAGE(0);
    asm volatile("cp.async.commit_group;" ::: "memory");

    for (int c = 0; c < nch; c++) {
        asm volatile("cp.async.wait_group 0;" ::: "memory");
        __syncthreads();

        if (c + 1 < nch) LOAD_STAGE(c + 1);
        asm volatile("cp.async.commit_group;" ::: "memory");

        const uint32_t st = sb + (c % STAGES) * STAGE_BYTES;
#pragma unroll
        for (int ks = 0; ks < 2; ks++) {
            uint32_t bhf[4][2], blf[4][2];
            const int rB0 = wn * 32 + (lane & 7);
            const int cuB = 2 * ks + ((lane >> 3) & 1);
#pragma unroll
            for (int fn = 0; fn < 4; fn++) {
                uint32_t ad = st + 16384 + swz(rB0 + 8 * fn, cuB);
                ldsm_x2(bhf[fn], ad);
                if (useBl) ldsm_x2(blf[fn], ad + 8192);
            }
#pragma unroll
            for (int fm = 0; fm < 4; fm++) {
                int rowA = wm * 64 + fm * 16 + (lane & 7) + ((lane >> 3) & 1) * 8;
                int cuA = 2 * ks + (lane >> 4);
                uint32_t ad = st + swz(rowA, cuA);
                uint32_t ah[4], al[4];
                ldsm_x4(ah, ad);
                if (useAl) ldsm_x4(al, ad + 8192);
#pragma unroll
                for (int fn = 0; fn < 4; fn++) mma_f16(acc[fm][fn], ah, bhf[fn]);
                if (useBl) {
#pragma unroll
                    for (int fn = 0; fn < 4; fn++) mma_f16(acc[fm][fn], ah, blf[fn]);
                }
                if (useAl) {
#pragma unroll
                    for (int fn = 0; fn < 4; fn++) mma_f16(acc[fm][fn], al, bhf[fn]);
                }
            }
        }
    }
#undef LOAD_STAGE

    // ---- epilogue ----
    const int eg = lane >> 2;
    const int et = lane & 3;

#pragma unroll
    for (int fm = 0; fm < 4; fm++) {
        size_t row0 = m0 + wm * 64 + fm * 16 + eg;
#pragma unroll
        for (int fn = 0; fn < 4; fn++) {
            size_t col = n0 + wn * 32 + fn * 8 + et * 2;
            float c0 = a * acc[fm][fn][0];
            float c1 = a * acc[fm][fn][1];
            float c2 = a * acc[fm][fn][2];
            float c3 = a * acc[fm][fn][3];
            if (emode == 0) {
                *(float2*)(Cf + cbase + row0 * N + col)       = make_float2(c0, c1);
                *(float2*)(Cf + cbase + (row0 + 8) * N + col) = make_float2(c2, c3);
            } else {
                uint32_t h0 = pack_h2(c0, c1);
                float2 e0 = unpack_h2(h0);
                uint32_t l0 = pack_h2(c0 - e0.x, c1 - e0.y);
                uint32_t h1 = pack_h2(c2, c3);
                float2 e1 = unpack_h2(h1);
                uint32_t l1 = pack_h2(c2 - e1.x, c3 - e1.y);
                *(uint32_t*)(Chi + cbase + row0 * N + col)       = h0;
                *(uint32_t*)(Clo + cbase + row0 * N + col)       = l0;
                *(uint32_t*)(Chi + cbase + (row0 + 8) * N + col) = h1;
                *(uint32_t*)(Clo + cbase + (row0 + 8) * N + col) = l1;
            }
        }
    }
}

// mode 0: fp32 out (alpha). mode 1: fp16 hi/lo out (alpha).
// mode 2: z=0 hi/lo out (alpha), z=1 fp32 out (alpha2); cbase 0.
template<int NP0, int NP1>
__global__ __launch_bounds__(256, 2)
void gemm_mma(const __half* __restrict__ Ah, const __half* __restrict__ Al,
              const __half* __restrict__ Bh, const __half* __restrict__ Bl,
              float* __restrict__ Cf, __half* __restrict__ Chi, __half* __restrict__ Clo,
              int M, int N, int K,
              long long sA, long long sB, long long sC,
              float alpha, float alpha2, int mode) {
    extern __shared__ __align__(16) char smem[];
    const uint32_t sb = smem_u32(smem);

    const int bz = blockIdx.z;
    const size_t m0 = (size_t)blockIdx.y * 128;
    const size_t n0 = (size_t)blockIdx.x * 128;

    const __half* gAh = Ah + (size_t)bz * (size_t)sA;
    const __half* gAl = Al + (size_t)bz * (size_t)sA;
    const __half* gBh = Bh + (size_t)bz * (size_t)sB;
    const __half* gBl = Bl + (size_t)bz * (size_t)sB;

    int emode = mode;
    float a = alpha;
    if (mode == 2) { emode = (bz == 0) ? 1 : 0; if (bz == 1) a = alpha2; }
    const size_t cbase = (mode == 2) ? 0 : (size_t)bz * (size_t)sC;

    if (bz == 0)
        gemm_core<NP0>(gAh, gAl, gBh, gBl, Cf, Chi, Clo, N, K, m0, n0, cbase, a, emode, sb);
    else
        gemm_core<NP1>(gAh, gAl, gBh, gBl, Cf, Chi, Clo, N, K, m0, n0, cbase, a, emode, sb);
}

// ---------------------------------------------------------------------------
// top-8 + softmax + weighted PV gather; writes final output (x0.5 folded in)
// ---------------------------------------------------------------------------
__global__ void topk_gather_kernel(float* __restrict__ out) {
    const int warp_global = (blockIdx.x * blockDim.x + threadIdx.x) >> 5;
    const int lane = threadIdx.x & 31;
    const int b = warp_global >> 11;
    const int t = warp_global & (TT - 1);

    const float* srow = g_scores + ((long)b * TT + t) * SS;

    float vals[8];
#pragma unroll
    for (int i = 0; i < 8; i++) vals[i] = srow[lane + 32 * i];

    float w[KTOP];
    int   idx[KTOP];

#pragma unroll
    for (int r = 0; r < KTOP; r++) {
        float best = -CUDART_INF_F;
        int   bi = 0x7fffffff;
#pragma unroll
        for (int i = 0; i < 8; i++)
            if (vals[i] > best) { best = vals[i]; bi = lane + 32 * i; }
#pragma unroll
        for (int off = 16; off; off >>= 1) {
            float ov = __shfl_xor_sync(0xffffffffu, best, off);
            int   oi = __shfl_xor_sync(0xffffffffu, bi, off);
            if (ov > best || (ov == best && oi < bi)) { best = ov; bi = oi; }
        }
        w[r] = best;
        idx[r] = bi;
#pragma unroll
        for (int i = 0; i < 8; i++)
            if ((lane + 32 * i) == bi) vals[i] = -CUDART_INF_F;
    }

    float mx = w[0];
    float sum = 0.f;
#pragma unroll
    for (int r = 0; r < KTOP; r++) { w[r] = __expf(w[r] - mx); sum += w[r]; }
    float inv = 0.5f / sum;                         // RETRIEVAL_WEIGHT folded in
#pragma unroll
    for (int r = 0; r < KTOP; r++) w[r] *= inv;

    const float* pvb = g_pv + (long)b * SS * CC;
    float* o = out + ((long)b * TT + t) * CC;
#pragma unroll
    for (int it = 0; it < CC / 128; it++) {
        int c = lane * 4 + it * 128;
        float4 acc = make_float4(0.f, 0.f, 0.f, 0.f);
#pragma unroll
        for (int r = 0; r < KTOP; r++) {
            float4 vv = *(const float4*)(pvb + (long)idx[r] * CC + c);
            acc.x = fmaf(w[r], vv.x, acc.x);
            acc.y = fmaf(w[r], vv.y, acc.y);
            acc.z = fmaf(w[r], vv.z, acc.z);
            acc.w = fmaf(w[r], vv.w, acc.w);
        }
        *(float4*)(o + c) = acc;
    }
}

// ---------------------------------------------------------------------------
// launch
// ---------------------------------------------------------------------------
extern "C" void kernel_launch(void* const* d_in, const int* in_sizes, int n_in,
                              void* d_out, int out_size) {
    const float* x  = (const float*)d_in[0];
    const float* Wq = (const float*)d_in[1];
    const float* Wk = (const float*)d_in[2];
    const float* Wv = (const float*)d_in[3];
    const float* Wp = (const float*)d_in[4];
    float* out = (float*)d_out;

    void *pxh, *pxl, *psh, *psl, *pkqh, *pkql, *ppv, *psc;
    void *pwah, *pwal, *pwbh, *pwbl, *pwgh, *pwgl;
    cudaGetSymbolAddress(&pxh, g_xh);  cudaGetSymbolAddress(&pxl, g_xl);
    cudaGetSymbolAddress(&psh, g_sh);  cudaGetSymbolAddress(&psl, g_sl);
    cudaGetSymbolAddress(&pkqh, g_kqh); cudaGetSymbolAddress(&pkql, g_kql);
    cudaGetSymbolAddress(&ppv, g_pv);  cudaGetSymbolAddress(&psc, g_scores);
    cudaGetSymbolAddress(&pwah, g_wah); cudaGetSymbolAddress(&pwal, g_wal);
    cudaGetSymbolAddress(&pwbh, g_wbh); cudaGetSymbolAddress(&pwbl, g_wbl);
    cudaGetSymbolAddress(&pwgh, g_wgh); cudaGetSymbolAddress(&pwgl, g_wgl);

    __half* xh = (__half*)pxh;  __half* xl = (__half*)pxl;
    __half* sh = (__half*)psh;  __half* sl = (__half*)psl;
    __half* kqh = (__half*)pkqh; __half* kql = (__half*)pkql;
    float* pv = (float*)ppv; float* scores = (float*)psc;
    __half* wah = (__half*)pwah; __half* wal = (__half*)pwal;
    __half* wbh = (__half*)pwbh; __half* wbl = (__half*)pwbl;
    __half* wgh = (__half*)pwgh; __half* wgl = (__half*)pwgl;

    cudaFuncSetAttribute(gemm_mma<3,3>, cudaFuncAttributeMaxDynamicSharedMemorySize, GEMM_SMEM);
    cudaFuncSetAttribute(gemm_mma<3,2>, cudaFuncAttributeMaxDynamicSharedMemorySize, GEMM_SMEM);
    cudaFuncSetAttribute(gemm_mma<3,1>, cudaFuncAttributeMaxDynamicSharedMemorySize, GEMM_SMEM);

    const long long CC2 = (long long)CC * CC;

    // 1) fused pool + x conversion; batched weight prep (Wq^T, Wk^T, Wv^T, Wp)
    pool_cvt_kernel<<<(BB * SS * CC) / 256, 256>>>(x);
    {
        dim3 tg(CC / 32, CC / 32, 4), tb(32, 8);
        weight_prep<<<tg, tb>>>(Wq, Wk, Wv, Wp);
    }

    // 2) weight products (batched z=2), hi/lo out, alpha=1 (keep x1024 scale):
    //    z=0: G' = (32Wq)^T·(32Wk), 3-product (feeds scores chain)
    //    z=1: H' = (32Wp)·(32Wv),   2-product (out path, loose budget)
    {
        dim3 grid(CC / 128, CC / 128, 2);
        gemm_mma<3,2><<<grid, 256, GEMM_SMEM>>>(wah, wal, wbh, wbl,
                                                nullptr, wgh, wgl, CC, CC, CC,
                                                CC2, CC2, CC2, 1.0f, 0.f, 1);
    }

    // 3) kq' + pv (batched z=2, mode 2):
    //    z=0: kq' = TN(slots, G') -> hi/lo, full 3-product (scores chain)
    //    z=1: pv  = TN(slots, H')·(1/1024) -> fp32, 1-product
    {
        dim3 grid(CC / 128, (BB * SS) / 128, 2);
        gemm_mma<3,1><<<grid, 256, GEMM_SMEM>>>(sh, sl, wgh, wgl,
                                                pv, kqh, kql, BB * SS, CC, CC,
                                                0, CC2, 0, 1.0f, 1.0f / 1024.0f, 2);
    }

    // 4) scores[b] = x[b] @ kq'[b]^T / (32*1024)  (batched over B, full 3-product)
    {
        dim3 grid(SS / 128, TT / 128, BB);
        gemm_mma<3,3><<<grid, 256, GEMM_SMEM>>>(xh, xl, kqh, kql, scores, nullptr, nullptr,
                                                TT, SS, CC,
                                                (long long)TT * CC, (long long)SS * CC, (long long)TT * SS,
                                                1.0f / 32768.0f, 0.f, 0);
    }

    // 5) top-8 + softmax + gather of pv -> out (0.5 folded in)
    topk_gather_kernel<<<(BB * TT) / 8, 256>>>(out);
}

// round 16
// speedup vs baseline: 1.5237x; 1.4129x over previous
#include <cuda_runtime.h>
#include <cuda_fp16.h>
#include <math_constants.h>
#include <cstdint>

#define BB 8
#define TT 2048
#define CC 1024
#define SS 256
#define KTOP 8

// ---------------------------------------------------------------------------
// helpers
// ---------------------------------------------------------------------------
__device__ __forceinline__ uint32_t smem_u32(const void* p) {
    uint32_t a;
    asm("{ .reg .u64 t; cvta.to.shared.u64 t, %1; cvt.u32.u64 %0, t; }" : "=r"(a) : "l"(p));
    return a;
}
__device__ __forceinline__ uint32_t pack_h2(float a, float b) {
    __half2 h = __floats2half2_rn(a, b);
    return *reinterpret_cast<uint32_t*>(&h);
}
__device__ __forceinline__ float2 unpack_h2(uint32_t u) {
    __half2 h = *reinterpret_cast<__half2*>(&u);
    return __half22float2(h);
}
__device__ __forceinline__ void mma_f16(float* d, const uint32_t* a, const uint32_t* b) {
    asm volatile(
        "mma.sync.aligned.m16n8k16.row.col.f32.f16.f16.f32 "
        "{%0,%1,%2,%3}, {%4,%5,%6,%7}, {%8,%9}, {%0,%1,%2,%3};"
        : "+f"(d[0]), "+f"(d[1]), "+f"(d[2]), "+f"(d[3])
        : "r"(a[0]), "r"(a[1]), "r"(a[2]), "r"(a[3]), "r"(b[0]), "r"(b[1]));
}
__device__ __forceinline__ void ldsm_x4(uint32_t* r, uint32_t addr) {
    asm volatile("ldmatrix.sync.aligned.m8n8.x4.shared.b16 {%0,%1,%2,%3}, [%4];"
        : "=r"(r[0]), "=r"(r[1]), "=r"(r[2]), "=r"(r[3]) : "r"(addr));
}
__device__ __forceinline__ void ldsm_x2(uint32_t* r, uint32_t addr) {
    asm volatile("ldmatrix.sync.aligned.m8n8.x2.shared.b16 {%0,%1}, [%2];"
        : "=r"(r[0]), "=r"(r[1]) : "r"(addr));
}
__device__ __forceinline__ void cp16(uint32_t saddr, const void* gaddr) {
    asm volatile("cp.async.cg.shared.global [%0], [%1], 16;" :: "r"(saddr), "l"(gaddr));
}
// swizzled byte offset within a tile region: row (64B pitch), 16B unit u (0..3)
__device__ __forceinline__ uint32_t swz(int row, int u) {
    return (uint32_t)(row * 64 + ((u ^ ((row >> 1) & 3)) << 4));
}

#define WSCALE 32.0f            // weight pre-scale (power of 2; exact)

// ---------------------------------------------------------------------------
// scratch
// ---------------------------------------------------------------------------
__device__ __half g_xh[BB * TT * CC];
__device__ __half g_xl[BB * TT * CC];
__device__ __half g_sh[BB * SS * CC];
__device__ __half g_sl[BB * SS * CC];
__device__ __half g_kqh[BB * SS * CC];      // kq' (scaled by 1024)
__device__ __half g_kql[BB * SS * CC];
__device__ float  g_pv[BB * SS * CC];       // pv (true scale)
__device__ float  g_scores[BB * TT * SS];
// A-buffer for weight products: slot0 = 32*Wq^T, slot1 = 32*Wp
__device__ __half g_wah[2 * CC * CC];
__device__ __half g_wal[2 * CC * CC];
// B-buffer: slot0 = 32*Wk^T, slot1 = 32*Wv^T
__device__ __half g_wbh[2 * CC * CC];
__device__ __half g_wbl[2 * CC * CC];
// products: slot0 = G' = 1024*Wq^T·Wk, slot1 = H' = 1024*Wp·Wv
__device__ __half g_wgh[2 * CC * CC];
__device__ __half g_wgl[2 * CC * CC];

// ---------------------------------------------------------------------------
// pool + x conversion body (runs as tail CTAs of a mega launch)
// ---------------------------------------------------------------------------
__device__ void pool_body(int pb, int npool, const float* __restrict__ x) {
    const int stride = npool * 256;
    for (int i = pb * 256 + threadIdx.x; i < BB * SS * CC; i += stride) {
        int c = i & (CC - 1);
        int bs = i >> 10;
        int s = bs & (SS - 1);
        int b = bs >> 8;
        const size_t base = ((size_t)b * TT + (size_t)s * 8) * CC + c;
        float sum = 0.f;
#pragma unroll
        for (int u = 0; u < 8; u++) {
            float v = x[base + (size_t)u * CC];
            sum += v;
            __half h = __float2half_rn(v);
            g_xh[base + (size_t)u * CC] = h;
            g_xl[base + (size_t)u * CC] = __float2half_rn(v - __half2float(h));
        }
        sum *= 0.125f;
        __half h = __float2half_rn(sum);
        g_sh[i] = h;
        g_sl[i] = __float2half_rn(sum - __half2float(h));
    }
}

// ---------------------------------------------------------------------------
// batched weight prep (z selects which weight)
// z=0: Wq^T -> wah/wal slot0;  z=1: Wk^T -> wbh/wbl slot0;
// z=2: Wv^T -> wbh/wbl slot1;  z=3: Wp (no transpose) -> wah/wal slot1
// ---------------------------------------------------------------------------
__global__ void weight_prep(const float* __restrict__ w0, const float* __restrict__ w1,
                            const float* __restrict__ w2, const float* __restrict__ w3) {
    __shared__ float t[32][33];
    const int z = blockIdx.z;
    const int bx = blockIdx.x * 32, by = blockIdx.y * 32;
    const int tx = threadIdx.x, ty = threadIdx.y;   // (32, 8)

    if (z == 3) {
        __half* oh = g_wah + (size_t)CC * CC;
        __half* ol = g_wal + (size_t)CC * CC;
#pragma unroll
        for (int j = 0; j < 4; j++) {
            size_t o = (size_t)(by + ty * 4 + j) * CC + bx + tx;
            float v = w3[o] * WSCALE;
            __half h = __float2half_rn(v);
            oh[o] = h;
            ol[o] = __float2half_rn(v - __half2float(h));
        }
        return;
    }

    const float* in = (z == 0) ? w0 : (z == 1) ? w1 : w2;
    __half* oh = (z == 0) ? g_wah : (z == 1) ? g_wbh : (g_wbh + (size_t)CC * CC);
    __half* ol = (z == 0) ? g_wal : (z == 1) ? g_wbl : (g_wbl + (size_t)CC * CC);

#pragma unroll
    for (int j = 0; j < 4; j++)
        t[ty * 4 + j][tx] = in[(size_t)(by + ty * 4 + j) * CC + bx + tx];
    __syncthreads();
#pragma unroll
    for (int j = 0; j < 4; j++) {
        float v = t[tx][ty * 4 + j] * WSCALE;
        __half h = __float2half_rn(v);
        size_t o = (size_t)(bx + ty * 4 + j) * CC + by + tx;
        oh[o] = h;
        ol[o] = __float2half_rn(v - __half2float(h));
    }
}

// ---------------------------------------------------------------------------
// R12-proven split-fp16 HMMA GEMM core. CTA 128x128, BK=32, 8 warps (2m x 4n),
// warp tile 64x32; 2-stage cp.async (64KB -> 2 CTAs/SM).
// full3 runtime flag (single guarded MMA block — the R12 pattern).
// ---------------------------------------------------------------------------
#define STAGES 2
#define STAGE_BYTES 32768
#define GEMM_SMEM (STAGES * STAGE_BYTES)

__device__ void gemm_core(
    const __half* __restrict__ gAh, const __half* __restrict__ gAl,
    const __half* __restrict__ gBh, const __half* __restrict__ gBl,
    float* __restrict__ Cf, __half* __restrict__ Chi, __half* __restrict__ Clo,
    int N, int K, size_t m0, size_t n0, size_t cbase,
    float a, int emode, bool full3, uint32_t sb) {

    const int tid = threadIdx.x;
    const int wid = tid >> 5;
    const int lane = tid & 31;

    const int lrow = tid >> 1;
    const int lu   = (tid & 1) * 2;
    const size_t aoffg = (m0 + lrow) * (size_t)K;
    const size_t boffg = (n0 + lrow) * (size_t)K;

    const int nch = K >> 5;

#define LOAD_STAGE(stg) do { \
    const uint32_t st = sb + ((stg) % STAGES) * STAGE_BYTES; \
    const int kof = (stg) * 32; \
    _Pragma("unroll") \
    for (int j = 0; j < 2; j++) { \
        int u = lu + j; \
        uint32_t so = swz(lrow, u); \
        size_t goa = aoffg + kof + u * 8; \
        size_t gob = boffg + kof + u * 8; \
        cp16(st + so,         gAh + goa); \
        cp16(st + 8192 + so,  gAl + goa); \
        cp16(st + 16384 + so, gBh + gob); \
        cp16(st + 24576 + so, gBl + gob); \
    } \
} while (0)

    const int wm = wid >> 2;
    const int wn = wid & 3;

    float acc[4][4][4];
#pragma unroll
    for (int i = 0; i < 4; i++)
#pragma unroll
        for (int j = 0; j < 4; j++)
#pragma unroll
            for (int r = 0; r < 4; r++) acc[i][j][r] = 0.f;

    LOAD_STAGE(0);
    asm volatile("cp.async.commit_group;" ::: "memory");

    for (int c = 0; c < nch; c++) {
        asm volatile("cp.async.wait_group 0;" ::: "memory");
        __syncthreads();

        if (c + 1 < nch) LOAD_STAGE(c + 1);
        asm volatile("cp.async.commit_group;" ::: "memory");

        const uint32_t st = sb + (c % STAGES) * STAGE_BYTES;
#pragma unroll
        for (int ks = 0; ks < 2; ks++) {
            uint32_t bhf[4][2], blf[4][2];
            const int rB0 = wn * 32 + (lane & 7);
            const int cuB = 2 * ks + ((lane >> 3) & 1);
#pragma unroll
            for (int fn = 0; fn < 4; fn++) {
                uint32_t ad = st + 16384 + swz(rB0 + 8 * fn, cuB);
                ldsm_x2(bhf[fn], ad);
                ldsm_x2(blf[fn], ad + 8192);
            }
#pragma unroll
            for (int fm = 0; fm < 4; fm++) {
                int rowA = wm * 64 + fm * 16 + (lane & 7) + ((lane >> 3) & 1) * 8;
                int cuA = 2 * ks + (lane >> 4);
                uint32_t ad = st + swz(rowA, cuA);
                uint32_t ah[4], al[4];
                ldsm_x4(ah, ad);
                ldsm_x4(al, ad + 8192);
#pragma unroll
                for (int fn = 0; fn < 4; fn++) mma_f16(acc[fm][fn], ah, bhf[fn]);
                if (full3) {
#pragma unroll
                    for (int fn = 0; fn < 4; fn++) mma_f16(acc[fm][fn], ah, blf[fn]);
                }
#pragma unroll
                for (int fn = 0; fn < 4; fn++) mma_f16(acc[fm][fn], al, bhf[fn]);
            }
        }
    }
#undef LOAD_STAGE

    // ---- epilogue ----
    const int eg = lane >> 2;
    const int et = lane & 3;

#pragma unroll
    for (int fm = 0; fm < 4; fm++) {
        size_t row0 = m0 + wm * 64 + fm * 16 + eg;
#pragma unroll
        for (int fn = 0; fn < 4; fn++) {
            size_t col = n0 + wn * 32 + fn * 8 + et * 2;
            float c0 = a * acc[fm][fn][0];
            float c1 = a * acc[fm][fn][1];
            float c2 = a * acc[fm][fn][2];
            float c3 = a * acc[fm][fn][3];
            if (emode == 0) {
                *(float2*)(Cf + cbase + row0 * N + col)       = make_float2(c0, c1);
                *(float2*)(Cf + cbase + (row0 + 8) * N + col) = make_float2(c2, c3);
            } else {
                uint32_t h0 = pack_h2(c0, c1);
                float2 e0 = unpack_h2(h0);
                uint32_t l0 = pack_h2(c0 - e0.x, c1 - e0.y);
                uint32_t h1 = pack_h2(c2, c3);
                float2 e1 = unpack_h2(h1);
                uint32_t l1 = pack_h2(c2 - e1.x, c3 - e1.y);
                *(uint32_t*)(Chi + cbase + row0 * N + col)       = h0;
                *(uint32_t*)(Clo + cbase + row0 * N + col)       = l0;
                *(uint32_t*)(Chi + cbase + (row0 + 8) * N + col) = h1;
                *(uint32_t*)(Clo + cbase + (row0 + 8) * N + col) = l1;
            }
        }
    }
}

// ---------------------------------------------------------------------------
// job descriptor + mega dispatcher (selection once at top; single core call)
// ---------------------------------------------------------------------------
struct GJob {
    const __half *Ah, *Al, *Bh, *Bl;
    float* Cf; __half *Chi, *Clo;
    int gx, gy;            // n-tiles, m-tiles
    int N, K;
    long long sA, sB, sC;  // per-z strides
    float alpha;
    int emode;             // 0 fp32 out, 1 fp16 hi/lo out
    int full3;
};

__global__ __launch_bounds__(256, 2)
void mega(GJob j0, GJob j1, int n0, int nGemm, int npool, const float* __restrict__ xin) {
    extern __shared__ __align__(16) char smem[];
    const int bid = blockIdx.x;
    if (bid >= nGemm) { pool_body(bid - nGemm, npool, xin); return; }

    const uint32_t sb = smem_u32(smem);
    const bool isA = bid < n0;
    const int rb = isA ? bid : bid - n0;

    const int gx = isA ? j0.gx : j1.gx;
    const int gy = isA ? j0.gy : j1.gy;
    const int nx = rb % gx;
    const int tt = rb / gx;
    const int my = tt % gy;
    const int z  = tt / gy;

    const long long sA = isA ? j0.sA : j1.sA;
    const long long sB = isA ? j0.sB : j1.sB;
    const long long sC = isA ? j0.sC : j1.sC;

    const __half* Ah = (isA ? j0.Ah : j1.Ah) + (size_t)z * (size_t)sA;
    const __half* Al = (isA ? j0.Al : j1.Al) + (size_t)z * (size_t)sA;
    const __half* Bh = (isA ? j0.Bh : j1.Bh) + (size_t)z * (size_t)sB;
    const __half* Bl = (isA ? j0.Bl : j1.Bl) + (size_t)z * (size_t)sB;
    float* Cf   = isA ? j0.Cf  : j1.Cf;
    __half* Chi = isA ? j0.Chi : j1.Chi;
    __half* Clo = isA ? j0.Clo : j1.Clo;
    const size_t cbase = (size_t)z * (size_t)sC;

    gemm_core(Ah, Al, Bh, Bl, Cf, Chi, Clo,
              isA ? j0.N : j1.N, isA ? j0.K : j1.K,
              (size_t)my * 128, (size_t)nx * 128, cbase,
              isA ? j0.alpha : j1.alpha, isA ? j0.emode : j1.emode,
              (isA ? j0.full3 : j1.full3) != 0, sb);
}

// ---------------------------------------------------------------------------
// top-8 + softmax + weighted PV gather; writes final output (x0.5 folded in)
// ---------------------------------------------------------------------------
__global__ void topk_gather_kernel(float* __restrict__ out) {
    const int warp_global = (blockIdx.x * blockDim.x + threadIdx.x) >> 5;
    const int lane = threadIdx.x & 31;
    const int b = warp_global >> 11;
    const int t = warp_global & (TT - 1);

    const float* srow = g_scores + ((long)b * TT + t) * SS;

    float vals[8];
#pragma unroll
    for (int i = 0; i < 8; i++) vals[i] = srow[lane + 32 * i];

    float w[KTOP];
    int   idx[KTOP];

#pragma unroll
    for (int r = 0; r < KTOP; r++) {
        float best = -CUDART_INF_F;
        int   bi = 0x7fffffff;
#pragma unroll
        for (int i = 0; i < 8; i++)
            if (vals[i] > best) { best = vals[i]; bi = lane + 32 * i; }
#pragma unroll
        for (int off = 16; off; off >>= 1) {
            float ov = __shfl_xor_sync(0xffffffffu, best, off);
            int   oi = __shfl_xor_sync(0xffffffffu, bi, off);
            if (ov > best || (ov == best && oi < bi)) { best = ov; bi = oi; }
        }
        w[r] = best;
        idx[r] = bi;
#pragma unroll
        for (int i = 0; i < 8; i++)
            if ((lane + 32 * i) == bi) vals[i] = -CUDART_INF_F;
    }

    float mx = w[0];
    float sum = 0.f;
#pragma unroll
    for (int r = 0; r < KTOP; r++) { w[r] = __expf(w[r] - mx); sum += w[r]; }
    float inv = 0.5f / sum;                         // RETRIEVAL_WEIGHT folded in
#pragma unroll
    for (int r = 0; r < KTOP; r++) w[r] *= inv;

    const float* pvb = g_pv + (long)b * SS * CC;
    float* o = out + ((long)b * TT + t) * CC;
#pragma unroll
    for (int it = 0; it < CC / 128; it++) {
        int c = lane * 4 + it * 128;
        float4 acc = make_float4(0.f, 0.f, 0.f, 0.f);
#pragma unroll
        for (int r = 0; r < KTOP; r++) {
            float4 vv = *(const float4*)(pvb + (long)idx[r] * CC + c);
            acc.x = fmaf(w[r], vv.x, acc.x);
            acc.y = fmaf(w[r], vv.y, acc.y);
            acc.z = fmaf(w[r], vv.z, acc.z);
            acc.w = fmaf(w[r], vv.w, acc.w);
        }
        *(float4*)(o + c) = acc;
    }
}

// ---------------------------------------------------------------------------
// launch
// ---------------------------------------------------------------------------
extern "C" void kernel_launch(void* const* d_in, const int* in_sizes, int n_in,
                              void* d_out, int out_size) {
    const float* x  = (const float*)d_in[0];
    const float* Wq = (const float*)d_in[1];
    const float* Wk = (const float*)d_in[2];
    const float* Wv = (const float*)d_in[3];
    const float* Wp = (const float*)d_in[4];
    float* out = (float*)d_out;

    void *pxh, *pxl, *psh, *psl, *pkqh, *pkql, *ppv, *psc;
    void *pwah, *pwal, *pwbh, *pwbl, *pwgh, *pwgl;
    cudaGetSymbolAddress(&pxh, g_xh);  cudaGetSymbolAddress(&pxl, g_xl);
    cudaGetSymbolAddress(&psh, g_sh);  cudaGetSymbolAddress(&psl, g_sl);
    cudaGetSymbolAddress(&pkqh, g_kqh); cudaGetSymbolAddress(&pkql, g_kql);
    cudaGetSymbolAddress(&ppv, g_pv);  cudaGetSymbolAddress(&psc, g_scores);
    cudaGetSymbolAddress(&pwah, g_wah); cudaGetSymbolAddress(&pwal, g_wal);
    cudaGetSymbolAddress(&pwbh, g_wbh); cudaGetSymbolAddress(&pwbl, g_wbl);
    cudaGetSymbolAddress(&pwgh, g_wgh); cudaGetSymbolAddress(&pwgl, g_wgl);

    __half* xh = (__half*)pxh;  __half* xl = (__half*)pxl;
    __half* sh = (__half*)psh;  __half* sl = (__half*)psl;
    __half* kqh = (__half*)pkqh; __half* kql = (__half*)pkql;
    float* pv = (float*)ppv; float* scores = (float*)psc;
    __half* wah = (__half*)pwah; __half* wal = (__half*)pwal;
    __half* wbh = (__half*)pwbh; __half* wbl = (__half*)pwbl;
    __half* wgh = (__half*)pwgh; __half* wgl = (__half*)pwgl;

    cudaFuncSetAttribute(mega, cudaFuncAttributeMaxDynamicSharedMemorySize, GEMM_SMEM);

    const long long CC2 = (long long)CC * CC;

    // jobs
    GJob jStep2 = { wah, wal, wbh, wbl, nullptr, wgh, wgl,
                    CC / 128, CC / 128, CC, CC, CC2, CC2, CC2, 1.0f, 1, 1 };
    GJob jKq    = { sh, sl, wgh, wgl, nullptr, kqh, kql,
                    CC / 128, (BB * SS) / 128, CC, CC, 0, 0, 0, 1.0f, 1, 1 };
    GJob jPv    = { sh, sl, wgh + CC2, wgl + CC2, pv, nullptr, nullptr,
                    CC / 128, (BB * SS) / 128, CC, CC, 0, 0, 0, 1.0f / 1024.0f, 0, 0 };
    GJob jScore = { xh, xl, kqh, kql, scores, nullptr, nullptr,
                    SS / 128, TT / 128, SS, CC,
                    (long long)TT * CC, (long long)SS * CC, (long long)TT * SS,
                    1.0f / 32768.0f, 0, 1 };

    // 1) weight prep (Wq^T, Wk^T, Wv^T, Wp -> scaled hi/lo)
    {
        dim3 tg(CC / 32, CC / 32, 4), tb(32, 8);
        weight_prep<<<tg, tb>>>(Wq, Wk, Wv, Wp);
    }

    // 2) [step2: G' + H' (128 CTAs)] ∥ [pool + x conversion (168 CTAs)]
    mega<<<296, 256, GEMM_SMEM>>>(jStep2, jStep2, 128, 128, 168, x);

    // 3) kq' = slots @ G'^T (hi/lo, 3-product) — 128 CTAs
    mega<<<128, 256, GEMM_SMEM>>>(jKq, jKq, 128, 128, 0, nullptr);

    // 4) [pv = slots @ H'^T (fp32, 2-product, 128 CTAs)] ∥ [scores (256 CTAs)]
    mega<<<384, 256, GEMM_SMEM>>>(jPv, jScore, 128, 384, 0, nullptr);

    // 5) top-8 + softmax + gather of pv -> out (0.5 folded in)
    topk_gather_kernel<<<(BB * TT) / 8, 256>>>(out);
}